// round 16
// baseline (speedup 1.0000x reference)
#include <cuda_runtime.h>
#include <cuda_fp16.h>
#include <math.h>
#include <cstdint>
#include <stdint.h>

#define SEQ 4096
#define CDIM 768
#define NH 12
#define HD 64
#define FDIM 3072
#define NQB (SEQ / 128)
#define NITEMS (NH * NQB)

// ---------------- scratch (device globals; no allocation allowed) ----------
__device__ __half g_q[SEQ * CDIM];
__device__ __half g_k[SEQ * CDIM];
__device__ __half g_v[SEQ * CDIM];
__device__ __half g_attn[SEQ * CDIM];
__device__ float  g_proj[SEQ * CDIM];
__device__ float  g_h[SEQ * CDIM];
__device__ __half g_hh[SEQ * CDIM];
__device__ __half g_mlp1[SEQ * FDIM];
__device__ float  g_mlp2[SEQ * CDIM];
__device__ __half g_xh[SEQ * CDIM];
__device__ __half g_wq[CDIM * CDIM];
__device__ __half g_wk[CDIM * CDIM];
__device__ __half g_wv[CDIM * CDIM];
__device__ __half g_wo[CDIM * CDIM];
__device__ __half g_w1[CDIM * FDIM];
__device__ __half g_w2[FDIM * CDIM];
__device__ int    g_ctr;

__device__ __forceinline__ void cp16(unsigned int dst, const void* src) {
    asm volatile("cp.async.cg.shared.global [%0], [%1], 16;" :: "r"(dst), "l"(src));
}
__device__ __forceinline__ void cp_commit() { asm volatile("cp.async.commit_group;"); }
__device__ __forceinline__ void cp_wait0() { asm volatile("cp.async.wait_group 0;"); }
__device__ __forceinline__ void cp_wait1() { asm volatile("cp.async.wait_group 1;"); }

__device__ __forceinline__ unsigned smem_u32(const void* p) {
    unsigned a;
    asm("{ .reg .u64 t; cvta.to.shared.u64 t, %1; cvt.u32.u64 %0, t; }" : "=r"(a) : "l"(p));
    return a;
}

__device__ __forceinline__ void mma_f16(
    float& d0, float& d1, float& d2, float& d3,
    unsigned a0, unsigned a1, unsigned a2, unsigned a3,
    unsigned b0, unsigned b1)
{
    asm volatile(
        "mma.sync.aligned.m16n8k16.row.col.f32.f16.f16.f32 "
        "{%0,%1,%2,%3},{%4,%5,%6,%7},{%8,%9},{%0,%1,%2,%3};"
        : "+f"(d0), "+f"(d1), "+f"(d2), "+f"(d3)
        : "r"(a0), "r"(a1), "r"(a2), "r"(a3), "r"(b0), "r"(b1));
}

__device__ __forceinline__ void ldsm4(
    unsigned& r0, unsigned& r1, unsigned& r2, unsigned& r3, unsigned addr)
{
    asm volatile("ldmatrix.sync.aligned.m8n8.x4.shared.b16 {%0,%1,%2,%3}, [%4];"
                 : "=r"(r0), "=r"(r1), "=r"(r2), "=r"(r3) : "r"(addr));
}

__device__ __forceinline__ void ldsm4t(
    unsigned& r0, unsigned& r1, unsigned& r2, unsigned& r3, unsigned addr)
{
    asm volatile("ldmatrix.sync.aligned.m8n8.x4.trans.shared.b16 {%0,%1,%2,%3}, [%4];"
                 : "=r"(r0), "=r"(r1), "=r"(r2), "=r"(r3) : "r"(addr));
}

__device__ __forceinline__ unsigned pack_h2(float lo, float hi) {
    __half2 h = __floats2half2_rn(lo, hi);
    return *reinterpret_cast<unsigned*>(&h);
}

// ---------------- fused float -> half converts (7 segments, 16 f/thread) ----
struct CvtSeg { const float* src; __half* dst; int n; };
struct CvtArgs { CvtSeg s[7]; };

__global__ __launch_bounds__(256) void cvt_all_kernel(CvtArgs a)
{
    const CvtSeg seg = a.s[blockIdx.y];
    const int base = (blockIdx.x * 256 + threadIdx.x) * 16;
#pragma unroll
    for (int j = 0; j < 4; j++) {
        const int i = base + j * 4;
        if (i < seg.n) {
            float4 v = *reinterpret_cast<const float4*>(seg.src + i);
            uint2 u;
            u.x = pack_h2(v.x, v.y);
            u.y = pack_h2(v.z, v.w);
            *reinterpret_cast<uint2*>(seg.dst + i) = u;
        }
    }
}

__global__ void reset_ctr_kernel() { g_ctr = 0; }

// ---------------- shared GEMM epilogue ---------------------------------------
template <bool GELU, typename OutT>
__device__ __forceinline__ void gemm_epilogue(
    float acc[2][4][4], const float* __restrict__ bias, OutT* __restrict__ C,
    int N, int bx, int by, int wm, int wn, int lane)
{
    const int g = lane >> 2, t = lane & 3;
#pragma unroll
    for (int mt = 0; mt < 2; mt++) {
        const int r0 = by * 64 + wm * 32 + mt * 16 + g;
#pragma unroll
        for (int nt = 0; nt < 4; nt++) {
            const int c0 = bx * 128 + wn * 32 + nt * 8 + t * 2;
            const float bz0 = bias[c0], bz1 = bias[c0 + 1];
            float v0 = acc[mt][nt][0] + bz0;
            float v1 = acc[mt][nt][1] + bz1;
            float v2 = acc[mt][nt][2] + bz0;
            float v3 = acc[mt][nt][3] + bz1;
            if (GELU) {
                v0 = 0.5f * v0 * (1.0f + erff(v0 * 0.70710678118654752f));
                v1 = 0.5f * v1 * (1.0f + erff(v1 * 0.70710678118654752f));
                v2 = 0.5f * v2 * (1.0f + erff(v2 * 0.70710678118654752f));
                v3 = 0.5f * v3 * (1.0f + erff(v3 * 0.70710678118654752f));
            }
            if (sizeof(OutT) == 2) {
                __half* Ch = reinterpret_cast<__half*>(C);
                *reinterpret_cast<unsigned*>(Ch + (size_t)r0 * N + c0) = pack_h2(v0, v1);
                *reinterpret_cast<unsigned*>(Ch + (size_t)(r0 + 8) * N + c0) = pack_h2(v2, v3);
            } else {
                float* Cf = reinterpret_cast<float*>(C);
                *reinterpret_cast<float2*>(Cf + (size_t)r0 * N + c0) = make_float2(v0, v1);
                *reinterpret_cast<float2*>(Cf + (size_t)(r0 + 8) * N + c0) = make_float2(v2, v3);
            }
        }
    }
}

// ---------------- GEMM body: 3-stage variant (small grids) -------------------
template <bool GELU, typename OutT>
__device__ __forceinline__ void gemm_body3(
    const __half* __restrict__ A, const __half* __restrict__ B,
    const float* __restrict__ bias, OutT* __restrict__ C,
    int N, int K, int bx, int by)
{
    constexpr int BM = 64, BK = 64;
    constexpr unsigned ABYTES = 64 * 128;
    constexpr unsigned STAGE = ABYTES + 64 * 256;   // 24576

    extern __shared__ __half smh[];
    const unsigned smb = smem_u32(smh);

    const int tid = threadIdx.x, lane = tid & 31, warp = tid >> 5;
    const int wm = warp & 1, wn = warp >> 1;

    const int lr = lane & 15;
    const int hi = lane >> 4;
    const int rx = lr & 7;

    unsigned arow[2];
#pragma unroll
    for (int mt = 0; mt < 2; mt++)
        arow[mt] = (unsigned)((wm * 32 + mt * 16 + lr) * 128);

    unsigned boff[2];
#pragma unroll
    for (int j = 0; j < 2; j++) {
        const int nunit = wn * 4 + j * 2 + hi;
        boff[j] = ABYTES + (unsigned)(lr * 256) + ((unsigned)(nunit ^ rx) << 4);
    }

    const int u0a = tid * 2;
    const int u0b = tid * 4;
    const __half* Abase = A + (size_t)(by * BM) * K;
    const __half* Bbase = B + (size_t)bx * 128;

    const int nchunks = K / BK;

    auto prefetch = [&](int ch) {
        const unsigned dst = smb + (unsigned)(ch % 3) * STAGE;
        const int k0 = ch * BK;
#pragma unroll
        for (int j = 0; j < 2; j++) {
            const int u = u0a + j, row = u >> 3, c16 = u & 7;
            cp16(dst + (unsigned)(row * 128) + ((unsigned)(c16 ^ (row & 7)) << 4),
                 Abase + (size_t)row * K + k0 + c16 * 8);
        }
#pragma unroll
        for (int j = 0; j < 4; j++) {
            const int u = u0b + j, row = u >> 4, c16 = u & 15;
            cp16(dst + ABYTES + (unsigned)(row * 256) + ((unsigned)(c16 ^ (row & 7)) << 4),
                 Bbase + (size_t)(k0 + row) * N + c16 * 8);
        }
        cp_commit();
    };

    float acc[2][4][4] = {};

    prefetch(0);
    prefetch(1);

    for (int ch = 0; ch < nchunks; ch++) {
        if (ch + 1 < nchunks) cp_wait1(); else cp_wait0();
        __syncthreads();
        if (ch + 2 < nchunks) prefetch(ch + 2);

        const unsigned sbase = smb + (unsigned)(ch % 3) * STAGE;
#pragma unroll
        for (int kk = 0; kk < 4; kk++) {
            unsigned af[2][4], bf[4][2];
            const unsigned aku = (unsigned)((kk * 2 + hi) ^ rx) << 4;
#pragma unroll
            for (int mt = 0; mt < 2; mt++)
                ldsm4(af[mt][0], af[mt][1], af[mt][2], af[mt][3],
                      sbase + arow[mt] + aku);
            const unsigned kadv = (unsigned)(kk * 16 * 256);
#pragma unroll
            for (int j = 0; j < 2; j++)
                ldsm4t(bf[2 * j][0], bf[2 * j][1], bf[2 * j + 1][0], bf[2 * j + 1][1],
                       sbase + boff[j] + kadv);
#pragma unroll
            for (int mt = 0; mt < 2; mt++)
#pragma unroll
                for (int nt = 0; nt < 4; nt++)
                    mma_f16(acc[mt][nt][0], acc[mt][nt][1], acc[mt][nt][2], acc[mt][nt][3],
                            af[mt][0], af[mt][1], af[mt][2], af[mt][3],
                            bf[nt][0], bf[nt][1]);
        }
    }

    gemm_epilogue<GELU, OutT>(acc, bias, C, N, bx, by, wm, wn, lane);
}

// ---------------- GEMM body: 2-stage variant (big grids) ---------------------
template <bool GELU, typename OutT>
__device__ __forceinline__ void gemm_body4(
    const __half* __restrict__ A, const __half* __restrict__ B,
    const float* __restrict__ bias, OutT* __restrict__ C,
    int N, int K, int bx, int by)
{
    constexpr int BM = 64, BK = 64;
    constexpr unsigned ABYTES = 64 * 128;
    constexpr unsigned STAGE = ABYTES + 64 * 256;   // 24576

    extern __shared__ __half smh[];
    const unsigned smb = smem_u32(smh);

    const int tid = threadIdx.x, lane = tid & 31, warp = tid >> 5;
    const int wm = warp & 1, wn = warp >> 1;

    const int lr = lane & 15;
    const int hi = lane >> 4;
    const int rx = lr & 7;

    const unsigned arow0 = (unsigned)((wm * 32 + lr) * 128);
    const unsigned arow1 = arow0 + 16 * 128;

    const unsigned brow = ABYTES + (unsigned)(lr * 256);
    const unsigned bu0 = ((unsigned)((wn * 4 + hi) ^ rx) << 4);
    const unsigned bu1 = ((unsigned)((wn * 4 + 2 + hi) ^ rx) << 4);

    const int u0a = tid * 2;
    const int u0b = tid * 4;
    const __half* Abase = A + (size_t)(by * BM) * K;
    const __half* Bbase = B + (size_t)bx * 128;

    const int nchunks = K / BK;

    auto prefetch = [&](int ch) {
        const unsigned dst = smb + (unsigned)(ch & 1) * STAGE;
        const int k0 = ch * BK;
#pragma unroll
        for (int j = 0; j < 2; j++) {
            const int u = u0a + j, row = u >> 3, c16 = u & 7;
            cp16(dst + (unsigned)(row * 128) + ((unsigned)(c16 ^ (row & 7)) << 4),
                 Abase + (size_t)row * K + k0 + c16 * 8);
        }
#pragma unroll
        for (int j = 0; j < 4; j++) {
            const int u = u0b + j, row = u >> 4, c16 = u & 15;
            cp16(dst + ABYTES + (unsigned)(row * 256) + ((unsigned)(c16 ^ (row & 7)) << 4),
                 Bbase + (size_t)(k0 + row) * N + c16 * 8);
        }
        cp_commit();
    };

    float acc[2][4][4] = {};

    prefetch(0);

    for (int ch = 0; ch < nchunks; ch++) {
        cp_wait0();
        __syncthreads();
        if (ch + 1 < nchunks) prefetch(ch + 1);

        const unsigned sbase = smb + (unsigned)(ch & 1) * STAGE;
#pragma unroll
        for (int kk = 0; kk < 4; kk++) {
            unsigned af[2][4], bf[4][2];
            const unsigned aku = (unsigned)((kk * 2 + hi) ^ rx) << 4;
            ldsm4(af[0][0], af[0][1], af[0][2], af[0][3], sbase + arow0 + aku);
            ldsm4(af[1][0], af[1][1], af[1][2], af[1][3], sbase + arow1 + aku);
            const unsigned kadv = (unsigned)(kk * 16 * 256);
            ldsm4t(bf[0][0], bf[0][1], bf[1][0], bf[1][1], sbase + brow + bu0 + kadv);
            ldsm4t(bf[2][0], bf[2][1], bf[3][0], bf[3][1], sbase + brow + bu1 + kadv);
#pragma unroll
            for (int mt = 0; mt < 2; mt++)
#pragma unroll
                for (int nt = 0; nt < 4; nt++)
                    mma_f16(acc[mt][nt][0], acc[mt][nt][1], acc[mt][nt][2], acc[mt][nt][3],
                            af[mt][0], af[mt][1], af[mt][2], af[mt][3],
                            bf[nt][0], bf[nt][1]);
        }
        __syncthreads();
    }

    gemm_epilogue<GELU, OutT>(acc, bias, C, N, bx, by, wm, wn, lane);
}

template <bool GELU, typename OutT>
__global__ __launch_bounds__(256, 3) void gemm_s(
    const __half* __restrict__ A, const __half* __restrict__ B,
    const float* __restrict__ bias, OutT* __restrict__ C, int N, int K)
{
    gemm_body3<GELU, OutT>(A, B, bias, C, N, K, blockIdx.x, blockIdx.y);
}

template <bool GELU, typename OutT>
__global__ __launch_bounds__(256, 4) void gemm_b(
    const __half* __restrict__ A, const __half* __restrict__ B,
    const float* __restrict__ bias, OutT* __restrict__ C, int N, int K)
{
    gemm_body4<GELU, OutT>(A, B, bias, C, N, K, blockIdx.x, blockIdx.y);
}

__global__ __launch_bounds__(256, 4) void gemm_b_qkv(
    const __half* __restrict__ X,
    const __half* __restrict__ Wqh, const __half* __restrict__ Wkh, const __half* __restrict__ Wvh,
    const float* __restrict__ bq, const float* __restrict__ bk, const float* __restrict__ bv,
    __half* __restrict__ q, __half* __restrict__ k, __half* __restrict__ v)
{
    const int which = blockIdx.x / 6;
    const int bx = blockIdx.x % 6;
    const __half* B   = (which == 0) ? Wqh : (which == 1) ? Wkh : Wvh;
    const float* bias = (which == 0) ? bq  : (which == 1) ? bk  : bv;
    __half* C         = (which == 0) ? q   : (which == 1) ? k   : v;
    gemm_body4<false, __half>(X, B, bias, C, CDIM, CDIM, bx, blockIdx.y);
}

// ---------------- persistent FP16 flash attention ----------------------------
// 296 persistent CTAs pull (h, qb) work items from a global counter, ordered
// heavy-first (descending qb across all heads). 3-stage cp.async K/V pipeline.
__global__ __launch_bounds__(256, 2) void flash_attn_p(
    const __half* __restrict__ Q, const __half* __restrict__ K,
    const __half* __restrict__ V, __half* __restrict__ O)
{
    constexpr int SR = 72;
    constexpr unsigned TILE = 64 * SR * 2;
    constexpr unsigned STAGE = 2 * TILE;

    extern __shared__ __half smh[];
    __shared__ int s_item;
    const unsigned kvb = smem_u32(smh);

    const int tid  = threadIdx.x;
    const int lane = tid & 31;
    const int w = tid >> 5;
    const int g = lane >> 2;
    const int t = lane & 3;

    // lane-constant ldmatrix offsets
    const int rb = (lane & 7) | ((lane & 16) >> 1);
    const int cbh = lane & 8;
    unsigned koff[4];
#pragma unroll
    for (int j = 0; j < 4; j++)
        koff[j] = ((j * 16 + rb) * SR + cbh) * 2;
    const int vr = lane & 15;
    const int vc = (lane >> 4) << 3;
    unsigned voff[4];
#pragma unroll
    for (int j = 0; j < 4; j++)
        voff[j] = TILE + (vr * SR + j * 16 + vc) * 2;

    const int u0 = tid * 2;

    for (;;) {
        if (tid == 0) s_item = atomicAdd(&g_ctr, 1);
        __syncthreads();
        const int item = s_item;
        if (item >= NITEMS) return;
        const int qb = (NQB - 1) - item / NH;   // heavy first
        const int h  = item % NH;

        const int r0 = qb * 128 + w * 16 + g;
        const int r1 = r0 + 8;

        // Q fragments, scaled by 1/8
        unsigned qf[4][4];
        {
            const __half2 sc = __float2half2_rn(0.125f);
            const __half* q0p = Q + (size_t)r0 * CDIM + h * HD;
            const __half* q1p = Q + (size_t)r1 * CDIM + h * HD;
#pragma unroll
            for (int kk = 0; kk < 4; kk++) {
                __half2 x0 = __hmul2(*reinterpret_cast<const __half2*>(q0p + kk * 16 + 2 * t), sc);
                __half2 x1 = __hmul2(*reinterpret_cast<const __half2*>(q1p + kk * 16 + 2 * t), sc);
                __half2 x2 = __hmul2(*reinterpret_cast<const __half2*>(q0p + kk * 16 + 2 * t + 8), sc);
                __half2 x3 = __hmul2(*reinterpret_cast<const __half2*>(q1p + kk * 16 + 2 * t + 8), sc);
                qf[kk][0] = *reinterpret_cast<unsigned*>(&x0);
                qf[kk][1] = *reinterpret_cast<unsigned*>(&x1);
                qf[kk][2] = *reinterpret_cast<unsigned*>(&x2);
                qf[kk][3] = *reinterpret_cast<unsigned*>(&x3);
            }
        }

        float o[8][4] = {};
        float m0 = -1e30f, m1 = -1e30f, l0 = 0.f, l1 = 0.f;

        const int ntiles = 2 * (qb + 1);

        auto prefetch = [&](int kb) {
            const unsigned dst = kvb + (unsigned)(kb % 3) * STAGE;
            const int kbase = kb * 64;
#pragma unroll
            for (int j = 0; j < 2; j++) {
                const int u = u0 + j, row = u >> 3, c = u & 7;
                const unsigned off = (unsigned)(row * SR + c * 8) * 2;
                cp16(dst + off, K + (size_t)(kbase + row) * CDIM + h * HD + c * 8);
                cp16(dst + TILE + off, V + (size_t)(kbase + row) * CDIM + h * HD + c * 8);
            }
            cp_commit();
        };

        prefetch(0);
        if (ntiles > 1) prefetch(1);

        for (int kb = 0; kb < ntiles; kb++) {
            if (kb + 1 < ntiles) cp_wait1(); else cp_wait0();
            __syncthreads();
            if (kb + 2 < ntiles) prefetch(kb + 2);

            const unsigned kbase_s = kvb + (unsigned)(kb % 3) * STAGE;

            float s[8][4] = {};
#pragma unroll
            for (int kk = 0; kk < 4; kk++) {
                const unsigned kb2 = kk * 32;
#pragma unroll
                for (int j = 0; j < 4; j++) {
                    unsigned b0, b1, b2, b3;
                    ldsm4(b0, b1, b2, b3, kbase_s + koff[j] + kb2);
                    mma_f16(s[2 * j][0], s[2 * j][1], s[2 * j][2], s[2 * j][3],
                            qf[kk][0], qf[kk][1], qf[kk][2], qf[kk][3], b0, b1);
                    mma_f16(s[2 * j + 1][0], s[2 * j + 1][1], s[2 * j + 1][2], s[2 * j + 1][3],
                            qf[kk][0], qf[kk][1], qf[kk][2], qf[kk][3], b2, b3);
                }
            }

            if (kb >= 2 * qb) {
                const int cb = kb * 64;
#pragma unroll
                for (int nt = 0; nt < 8; nt++) {
                    const int c0 = cb + nt * 8 + 2 * t;
                    if (c0 > r0)     s[nt][0] = -1e30f;
                    if (c0 + 1 > r0) s[nt][1] = -1e30f;
                    if (c0 > r1)     s[nt][2] = -1e30f;
                    if (c0 + 1 > r1) s[nt][3] = -1e30f;
                }
            }

            float mx0 = -1e30f, mx1 = -1e30f;
#pragma unroll
            for (int nt = 0; nt < 8; nt++) {
                mx0 = fmaxf(mx0, fmaxf(s[nt][0], s[nt][1]));
                mx1 = fmaxf(mx1, fmaxf(s[nt][2], s[nt][3]));
            }
            mx0 = fmaxf(mx0, __shfl_xor_sync(0xffffffffu, mx0, 1));
            mx0 = fmaxf(mx0, __shfl_xor_sync(0xffffffffu, mx0, 2));
            mx1 = fmaxf(mx1, __shfl_xor_sync(0xffffffffu, mx1, 1));
            mx1 = fmaxf(mx1, __shfl_xor_sync(0xffffffffu, mx1, 2));

            const float nm0 = fmaxf(m0, mx0);
            const float nm1 = fmaxf(m1, mx1);
            const float cr0 = __expf(m0 - nm0);
            const float cr1 = __expf(m1 - nm1);
            m0 = nm0; m1 = nm1;

            float sm0 = 0.f, sm1 = 0.f;
#pragma unroll
            for (int nt = 0; nt < 8; nt++) {
                float p0 = __expf(s[nt][0] - nm0);
                float p1 = __expf(s[nt][1] - nm0);
                float p2 = __expf(s[nt][2] - nm1);
                float p3 = __expf(s[nt][3] - nm1);
                s[nt][0] = p0; s[nt][1] = p1; s[nt][2] = p2; s[nt][3] = p3;
                sm0 += p0 + p1;
                sm1 += p2 + p3;
            }
            sm0 += __shfl_xor_sync(0xffffffffu, sm0, 1);
            sm0 += __shfl_xor_sync(0xffffffffu, sm0, 2);
            sm1 += __shfl_xor_sync(0xffffffffu, sm1, 1);
            sm1 += __shfl_xor_sync(0xffffffffu, sm1, 2);
            l0 = l0 * cr0 + sm0;
            l1 = l1 * cr1 + sm1;

#pragma unroll
            for (int nt = 0; nt < 8; nt++) {
                o[nt][0] *= cr0; o[nt][1] *= cr0;
                o[nt][2] *= cr1; o[nt][3] *= cr1;
            }

#pragma unroll
            for (int kk = 0; kk < 4; kk++) {
                unsigned a0 = pack_h2(s[2 * kk][0], s[2 * kk][1]);
                unsigned a1 = pack_h2(s[2 * kk][2], s[2 * kk][3]);
                unsigned a2 = pack_h2(s[2 * kk + 1][0], s[2 * kk + 1][1]);
                unsigned a3 = pack_h2(s[2 * kk + 1][2], s[2 * kk + 1][3]);
                const unsigned kb2 = kk * 16 * SR * 2;
#pragma unroll
                for (int j = 0; j < 4; j++) {
                    unsigned b0, b1, b2, b3;
                    ldsm4t(b0, b1, b2, b3, kbase_s + voff[j] + kb2);
                    mma_f16(o[2 * j][0], o[2 * j][1], o[2 * j][2], o[2 * j][3],
                            a0, a1, a2, a3, b0, b1);
                    mma_f16(o[2 * j + 1][0], o[2 * j + 1][1], o[2 * j + 1][2], o[2 * j + 1][3],
                            a0, a1, a2, a3, b2, b3);
                }
            }
        }

        const float inv0 = 1.f / l0;
        const float inv1 = 1.f / l1;
        __half* o0p = O + (size_t)r0 * CDIM + h * HD;
        __half* o1p = O + (size_t)r1 * CDIM + h * HD;
#pragma unroll
        for (int nt = 0; nt < 8; nt++) {
            const int c = nt * 8 + 2 * t;
            *reinterpret_cast<unsigned*>(o0p + c) = pack_h2(o[nt][0] * inv0, o[nt][1] * inv0);
            *reinterpret_cast<unsigned*>(o1p + c) = pack_h2(o[nt][2] * inv1, o[nt][3] * inv1);
        }
        __syncthreads();   // smem + s_item safe for next item
    }
}

// ---------------- fused residual add + LayerNorm (vectorized) ---------------
template <bool DUALOUT>
__global__ __launch_bounds__(256) void add_ln(
    const float* __restrict__ A, const float* __restrict__ Bb,
    const float* __restrict__ g, const float* __restrict__ be,
    float* __restrict__ out, __half* __restrict__ out_h)
{
    const int row = blockIdx.x;
    const int tid = threadIdx.x;
    const float* pa = A + (size_t)row * CDIM;
    const float* pb = Bb + (size_t)row * CDIM;

    float4 v = make_float4(0.f, 0.f, 0.f, 0.f);
    float s = 0.f, sq = 0.f;
    if (tid < 192) {
        float4 a = *reinterpret_cast<const float4*>(pa + tid * 4);
        float4 b = *reinterpret_cast<const float4*>(pb + tid * 4);
        v.x = a.x + b.x; v.y = a.y + b.y; v.z = a.z + b.z; v.w = a.w + b.w;
        s = v.x + v.y + v.z + v.w;
        sq = v.x * v.x + v.y * v.y + v.z * v.z + v.w * v.w;
    }
#pragma unroll
    for (int off = 16; off; off >>= 1) {
        s += __shfl_xor_sync(0xffffffffu, s, off);
        sq += __shfl_xor_sync(0xffffffffu, sq, off);
    }
    __shared__ float ss[8], ssq[8];
    int w = tid >> 5, lane = tid & 31;
    if (lane == 0) { ss[w] = s; ssq[w] = sq; }
    __syncthreads();
    if (tid < 32) {
        s = (tid < 8) ? ss[tid] : 0.f;
        sq = (tid < 8) ? ssq[tid] : 0.f;
#pragma unroll
        for (int off = 4; off; off >>= 1) {
            s += __shfl_xor_sync(0xffffffffu, s, off);
            sq += __shfl_xor_sync(0xffffffffu, sq, off);
        }
        if (tid == 0) { ss[0] = s; ssq[0] = sq; }
    }
    __syncthreads();
    const float mean = ss[0] * (1.0f / CDIM);
    const float var = ssq[0] * (1.0f / CDIM) - mean * mean;
    const float inv = rsqrtf(var + 1e-5f);
    if (tid < 192) {
        float4 gg = *reinterpret_cast<const float4*>(g + tid * 4);
        float4 bb = *reinterpret_cast<const float4*>(be + tid * 4);
        float4 r;
        r.x = (v.x - mean) * inv * gg.x + bb.x;
        r.y = (v.y - mean) * inv * gg.y + bb.y;
        r.z = (v.z - mean) * inv * gg.z + bb.z;
        r.w = (v.w - mean) * inv * gg.w + bb.w;
        *reinterpret_cast<float4*>(out + (size_t)row * CDIM + tid * 4) = r;
        if (DUALOUT) {
            uint2 u;
            u.x = pack_h2(r.x, r.y);
            u.y = pack_h2(r.z, r.w);
            *reinterpret_cast<uint2*>(out_h + (size_t)row * CDIM + tid * 4) = u;
        }
    }
}

// ---------------- launch ----------------------------------------------------
extern "C" void kernel_launch(void* const* d_in, const int* in_sizes, int n_in,
                              void* d_out, int out_size)
{
    const float* x     = (const float*)d_in[0];
    const float* Wq    = (const float*)d_in[1];
    const float* bq    = (const float*)d_in[2];
    const float* Wk    = (const float*)d_in[3];
    const float* bk    = (const float*)d_in[4];
    const float* Wv    = (const float*)d_in[5];
    const float* bv    = (const float*)d_in[6];
    const float* Wo    = (const float*)d_in[7];
    const float* bo    = (const float*)d_in[8];
    const float* ln1g  = (const float*)d_in[9];
    const float* ln1b  = (const float*)d_in[10];
    const float* W1    = (const float*)d_in[11];
    const float* b1    = (const float*)d_in[12];
    const float* W2    = (const float*)d_in[13];
    const float* b2    = (const float*)d_in[14];
    const float* ln2g  = (const float*)d_in[15];
    const float* ln2b  = (const float*)d_in[16];
    float* y = (float*)d_out;

    __half *q, *k, *v, *attn, *hh, *m1, *xh, *wq, *wk, *wv, *wo, *w1, *w2;
    float *proj, *h, *m2;
    cudaGetSymbolAddress((void**)&q,    g_q);
    cudaGetSymbolAddress((void**)&k,    g_k);
    cudaGetSymbolAddress((void**)&v,    g_v);
    cudaGetSymbolAddress((void**)&attn, g_attn);
    cudaGetSymbolAddress((void**)&proj, g_proj);
    cudaGetSymbolAddress((void**)&h,    g_h);
    cudaGetSymbolAddress((void**)&hh,   g_hh);
    cudaGetSymbolAddress((void**)&m1,   g_mlp1);
    cudaGetSymbolAddress((void**)&m2,   g_mlp2);
    cudaGetSymbolAddress((void**)&xh,   g_xh);
    cudaGetSymbolAddress((void**)&wq,   g_wq);
    cudaGetSymbolAddress((void**)&wk,   g_wk);
    cudaGetSymbolAddress((void**)&wv,   g_wv);
    cudaGetSymbolAddress((void**)&wo,   g_wo);
    cudaGetSymbolAddress((void**)&w1,   g_w1);
    cudaGetSymbolAddress((void**)&w2,   g_w2);

    const int SMEM_S  = 3 * 24576;              // 73728 (3-stage)
    const int SMEM_B  = 2 * 24576;              // 49152 (2-stage)
    const int SMEM_FA = 3 * 2 * 64 * 72 * 2;    // 55296
    cudaFuncSetAttribute(gemm_b_qkv, cudaFuncAttributeMaxDynamicSharedMemorySize, SMEM_B);
    cudaFuncSetAttribute(gemm_b<true, __half>,  cudaFuncAttributeMaxDynamicSharedMemorySize, SMEM_B);
    cudaFuncSetAttribute(gemm_s<false, float>,  cudaFuncAttributeMaxDynamicSharedMemorySize, SMEM_S);
    cudaFuncSetAttribute(flash_attn_p, cudaFuncAttributeMaxDynamicSharedMemorySize, SMEM_FA);

    // one fused convert launch: x + 6 weights -> half
    CvtArgs ca;
    ca.s[0] = { x,  xh, SEQ * CDIM };
    ca.s[1] = { Wq, wq, CDIM * CDIM };
    ca.s[2] = { Wk, wk, CDIM * CDIM };
    ca.s[3] = { Wv, wv, CDIM * CDIM };
    ca.s[4] = { Wo, wo, CDIM * CDIM };
    ca.s[5] = { W1, w1, CDIM * FDIM };
    ca.s[6] = { W2, w2, FDIM * CDIM };
    cvt_all_kernel<<<dim3(SEQ * CDIM / 4096, 7), 256>>>(ca);

    // fused QKV projection (big grid: 2-stage, 4 CTA/SM)
    gemm_b_qkv<<<dim3(18, SEQ / 64), 256, SMEM_B>>>(xh, wq, wk, wv, bq, bk, bv, q, k, v);

    // causal attention: persistent work-stealing (2 CTAs/SM x 148 SMs)
    reset_ctr_kernel<<<1, 1>>>();
    flash_attn_p<<<296, 256, SMEM_FA>>>(q, k, v, attn);

    // output projection (small grid: 3-stage, 3 CTA/SM)
    gemm_s<false, float><<<dim3(CDIM / 128, SEQ / 64), 256, SMEM_S>>>(attn, wo, bo, proj, CDIM, CDIM);

    // h = LN(x + proj), plus half copy for W1
    add_ln<true><<<SEQ, 256>>>(x, proj, ln1g, ln1b, h, hh);

    // MLP1 (big grid) / MLP2 (small grid)
    gemm_b<true, __half><<<dim3(FDIM / 128, SEQ / 64), 256, SMEM_B>>>(hh, w1, b1, m1, FDIM, CDIM);
    gemm_s<false, float><<<dim3(CDIM / 128, SEQ / 64), 256, SMEM_S>>>(m1, w2, b2, m2, CDIM, FDIM);

    // y = LN(h + mlp)
    add_ln<false><<<SEQ, 256>>>(h, m2, ln2g, ln2b, y, nullptr);

    (void)in_sizes; (void)n_in; (void)out_size;
}

// round 17
// speedup vs baseline: 1.3846x; 1.3846x over previous
#include <cuda_runtime.h>
#include <cuda_fp16.h>
#include <math.h>
#include <cstdint>
#include <stdint.h>

#define SEQ 4096
#define CDIM 768
#define NH 12
#define HD 64
#define FDIM 3072

// ---------------- scratch (device globals; no allocation allowed) ----------
__device__ __half g_q[SEQ * CDIM];
__device__ __half g_k[SEQ * CDIM];
__device__ __half g_v[SEQ * CDIM];
__device__ __half g_attn[SEQ * CDIM];
__device__ float  g_proj[SEQ * CDIM];
__device__ float  g_h[SEQ * CDIM];
__device__ __half g_hh[SEQ * CDIM];
__device__ __half g_mlp1[SEQ * FDIM];
__device__ float  g_mlp2[SEQ * CDIM];
__device__ __half g_xh[SEQ * CDIM];
__device__ __half g_wq[CDIM * CDIM];
__device__ __half g_wk[CDIM * CDIM];
__device__ __half g_wv[CDIM * CDIM];
__device__ __half g_wo[CDIM * CDIM];
__device__ __half g_w1[CDIM * FDIM];
__device__ __half g_w2[FDIM * CDIM];

__device__ __forceinline__ void cp16(unsigned int dst, const void* src) {
    asm volatile("cp.async.cg.shared.global [%0], [%1], 16;" :: "r"(dst), "l"(src));
}
__device__ __forceinline__ void cp_commit() { asm volatile("cp.async.commit_group;"); }
__device__ __forceinline__ void cp_wait0() { asm volatile("cp.async.wait_group 0;"); }
__device__ __forceinline__ void cp_wait1() { asm volatile("cp.async.wait_group 1;"); }

__device__ __forceinline__ unsigned smem_u32(const void* p) {
    unsigned a;
    asm("{ .reg .u64 t; cvta.to.shared.u64 t, %1; cvt.u32.u64 %0, t; }" : "=r"(a) : "l"(p));
    return a;
}

__device__ __forceinline__ void mma_f16(
    float& d0, float& d1, float& d2, float& d3,
    unsigned a0, unsigned a1, unsigned a2, unsigned a3,
    unsigned b0, unsigned b1)
{
    asm volatile(
        "mma.sync.aligned.m16n8k16.row.col.f32.f16.f16.f32 "
        "{%0,%1,%2,%3},{%4,%5,%6,%7},{%8,%9},{%0,%1,%2,%3};"
        : "+f"(d0), "+f"(d1), "+f"(d2), "+f"(d3)
        : "r"(a0), "r"(a1), "r"(a2), "r"(a3), "r"(b0), "r"(b1));
}

__device__ __forceinline__ void ldsm4(
    unsigned& r0, unsigned& r1, unsigned& r2, unsigned& r3, unsigned addr)
{
    asm volatile("ldmatrix.sync.aligned.m8n8.x4.shared.b16 {%0,%1,%2,%3}, [%4];"
                 : "=r"(r0), "=r"(r1), "=r"(r2), "=r"(r3) : "r"(addr));
}

__device__ __forceinline__ void ldsm4t(
    unsigned& r0, unsigned& r1, unsigned& r2, unsigned& r3, unsigned addr)
{
    asm volatile("ldmatrix.sync.aligned.m8n8.x4.trans.shared.b16 {%0,%1,%2,%3}, [%4];"
                 : "=r"(r0), "=r"(r1), "=r"(r2), "=r"(r3) : "r"(addr));
}

__device__ __forceinline__ unsigned pack_h2(float lo, float hi) {
    __half2 h = __floats2half2_rn(lo, hi);
    return *reinterpret_cast<unsigned*>(&h);
}

// ---------------- fused float -> half converts (7 segments, 16 f/thread) ----
struct CvtSeg { const float* src; __half* dst; int n; };
struct CvtArgs { CvtSeg s[7]; };

__global__ __launch_bounds__(256) void cvt_all_kernel(CvtArgs a)
{
    const CvtSeg seg = a.s[blockIdx.y];
    const int base = (blockIdx.x * 256 + threadIdx.x) * 16;
#pragma unroll
    for (int j = 0; j < 4; j++) {
        const int i = base + j * 4;
        if (i < seg.n) {
            float4 v = *reinterpret_cast<const float4*>(seg.src + i);
            uint2 u;
            u.x = pack_h2(v.x, v.y);
            u.y = pack_h2(v.z, v.w);
            *reinterpret_cast<uint2*>(seg.dst + i) = u;
        }
    }
}

// ---------------- shared GEMM epilogue ---------------------------------------
template <bool GELU, typename OutT>
__device__ __forceinline__ void gemm_epilogue(
    float acc[2][4][4], const float* __restrict__ bias, OutT* __restrict__ C,
    int N, int bx, int by, int wm, int wn, int lane)
{
    const int g = lane >> 2, t = lane & 3;
#pragma unroll
    for (int mt = 0; mt < 2; mt++) {
        const int r0 = by * 64 + wm * 32 + mt * 16 + g;
#pragma unroll
        for (int nt = 0; nt < 4; nt++) {
            const int c0 = bx * 128 + wn * 32 + nt * 8 + t * 2;
            const float bz0 = bias[c0], bz1 = bias[c0 + 1];
            float v0 = acc[mt][nt][0] + bz0;
            float v1 = acc[mt][nt][1] + bz1;
            float v2 = acc[mt][nt][2] + bz0;
            float v3 = acc[mt][nt][3] + bz1;
            if (GELU) {
                v0 = 0.5f * v0 * (1.0f + erff(v0 * 0.70710678118654752f));
                v1 = 0.5f * v1 * (1.0f + erff(v1 * 0.70710678118654752f));
                v2 = 0.5f * v2 * (1.0f + erff(v2 * 0.70710678118654752f));
                v3 = 0.5f * v3 * (1.0f + erff(v3 * 0.70710678118654752f));
            }
            if (sizeof(OutT) == 2) {
                __half* Ch = reinterpret_cast<__half*>(C);
                *reinterpret_cast<unsigned*>(Ch + (size_t)r0 * N + c0) = pack_h2(v0, v1);
                *reinterpret_cast<unsigned*>(Ch + (size_t)(r0 + 8) * N + c0) = pack_h2(v2, v3);
            } else {
                float* Cf = reinterpret_cast<float*>(C);
                *reinterpret_cast<float2*>(Cf + (size_t)r0 * N + c0) = make_float2(v0, v1);
                *reinterpret_cast<float2*>(Cf + (size_t)(r0 + 8) * N + c0) = make_float2(v2, v3);
            }
        }
    }
}

// ---------------- GEMM body: 3-stage variant (small grids) -------------------
template <bool GELU, typename OutT>
__device__ __forceinline__ void gemm_body3(
    const __half* __restrict__ A, const __half* __restrict__ B,
    const float* __restrict__ bias, OutT* __restrict__ C,
    int N, int K, int bx, int by)
{
    constexpr int BM = 64, BK = 64;
    constexpr unsigned ABYTES = 64 * 128;
    constexpr unsigned STAGE = ABYTES + 64 * 256;   // 24576

    extern __shared__ __half smh[];
    const unsigned smb = smem_u32(smh);

    const int tid = threadIdx.x, lane = tid & 31, warp = tid >> 5;
    const int wm = warp & 1, wn = warp >> 1;

    const int lr = lane & 15;
    const int hi = lane >> 4;
    const int rx = lr & 7;

    unsigned arow[2];
#pragma unroll
    for (int mt = 0; mt < 2; mt++)
        arow[mt] = (unsigned)((wm * 32 + mt * 16 + lr) * 128);

    unsigned boff[2];
#pragma unroll
    for (int j = 0; j < 2; j++) {
        const int nunit = wn * 4 + j * 2 + hi;
        boff[j] = ABYTES + (unsigned)(lr * 256) + ((unsigned)(nunit ^ rx) << 4);
    }

    const int u0a = tid * 2;
    const int u0b = tid * 4;
    const __half* Abase = A + (size_t)(by * BM) * K;
    const __half* Bbase = B + (size_t)bx * 128;

    const int nchunks = K / BK;

    auto prefetch = [&](int ch) {
        const unsigned dst = smb + (unsigned)(ch % 3) * STAGE;
        const int k0 = ch * BK;
#pragma unroll
        for (int j = 0; j < 2; j++) {
            const int u = u0a + j, row = u >> 3, c16 = u & 7;
            cp16(dst + (unsigned)(row * 128) + ((unsigned)(c16 ^ (row & 7)) << 4),
                 Abase + (size_t)row * K + k0 + c16 * 8);
        }
#pragma unroll
        for (int j = 0; j < 4; j++) {
            const int u = u0b + j, row = u >> 4, c16 = u & 15;
            cp16(dst + ABYTES + (unsigned)(row * 256) + ((unsigned)(c16 ^ (row & 7)) << 4),
                 Bbase + (size_t)(k0 + row) * N + c16 * 8);
        }
        cp_commit();
    };

    float acc[2][4][4] = {};

    prefetch(0);
    prefetch(1);

    for (int ch = 0; ch < nchunks; ch++) {
        if (ch + 1 < nchunks) cp_wait1(); else cp_wait0();
        __syncthreads();
        if (ch + 2 < nchunks) prefetch(ch + 2);

        const unsigned sbase = smb + (unsigned)(ch % 3) * STAGE;
#pragma unroll
        for (int kk = 0; kk < 4; kk++) {
            unsigned af[2][4], bf[4][2];
            const unsigned aku = (unsigned)((kk * 2 + hi) ^ rx) << 4;
#pragma unroll
            for (int mt = 0; mt < 2; mt++)
                ldsm4(af[mt][0], af[mt][1], af[mt][2], af[mt][3],
                      sbase + arow[mt] + aku);
            const unsigned kadv = (unsigned)(kk * 16 * 256);
#pragma unroll
            for (int j = 0; j < 2; j++)
                ldsm4t(bf[2 * j][0], bf[2 * j][1], bf[2 * j + 1][0], bf[2 * j + 1][1],
                       sbase + boff[j] + kadv);
#pragma unroll
            for (int mt = 0; mt < 2; mt++)
#pragma unroll
                for (int nt = 0; nt < 4; nt++)
                    mma_f16(acc[mt][nt][0], acc[mt][nt][1], acc[mt][nt][2], acc[mt][nt][3],
                            af[mt][0], af[mt][1], af[mt][2], af[mt][3],
                            bf[nt][0], bf[nt][1]);
        }
    }

    gemm_epilogue<GELU, OutT>(acc, bias, C, N, bx, by, wm, wn, lane);
}

// ---------------- GEMM body: 2-stage variant (big grids) ---------------------
template <bool GELU, typename OutT>
__device__ __forceinline__ void gemm_body4(
    const __half* __restrict__ A, const __half* __restrict__ B,
    const float* __restrict__ bias, OutT* __restrict__ C,
    int N, int K, int bx, int by)
{
    constexpr int BM = 64, BK = 64;
    constexpr unsigned ABYTES = 64 * 128;
    constexpr unsigned STAGE = ABYTES + 64 * 256;   // 24576

    extern __shared__ __half smh[];
    const unsigned smb = smem_u32(smh);

    const int tid = threadIdx.x, lane = tid & 31, warp = tid >> 5;
    const int wm = warp & 1, wn = warp >> 1;

    const int lr = lane & 15;
    const int hi = lane >> 4;
    const int rx = lr & 7;

    const unsigned arow0 = (unsigned)((wm * 32 + lr) * 128);
    const unsigned arow1 = arow0 + 16 * 128;

    const unsigned brow = ABYTES + (unsigned)(lr * 256);
    const unsigned bu0 = ((unsigned)((wn * 4 + hi) ^ rx) << 4);
    const unsigned bu1 = ((unsigned)((wn * 4 + 2 + hi) ^ rx) << 4);

    const int u0a = tid * 2;
    const int u0b = tid * 4;
    const __half* Abase = A + (size_t)(by * BM) * K;
    const __half* Bbase = B + (size_t)bx * 128;

    const int nchunks = K / BK;

    auto prefetch = [&](int ch) {
        const unsigned dst = smb + (unsigned)(ch & 1) * STAGE;
        const int k0 = ch * BK;
#pragma unroll
        for (int j = 0; j < 2; j++) {
            const int u = u0a + j, row = u >> 3, c16 = u & 7;
            cp16(dst + (unsigned)(row * 128) + ((unsigned)(c16 ^ (row & 7)) << 4),
                 Abase + (size_t)row * K + k0 + c16 * 8);
        }
#pragma unroll
        for (int j = 0; j < 4; j++) {
            const int u = u0b + j, row = u >> 4, c16 = u & 15;
            cp16(dst + ABYTES + (unsigned)(row * 256) + ((unsigned)(c16 ^ (row & 7)) << 4),
                 Bbase + (size_t)(k0 + row) * N + c16 * 8);
        }
        cp_commit();
    };

    float acc[2][4][4] = {};

    prefetch(0);

    for (int ch = 0; ch < nchunks; ch++) {
        cp_wait0();
        __syncthreads();
        if (ch + 1 < nchunks) prefetch(ch + 1);

        const unsigned sbase = smb + (unsigned)(ch & 1) * STAGE;
#pragma unroll
        for (int kk = 0; kk < 4; kk++) {
            unsigned af[2][4], bf[4][2];
            const unsigned aku = (unsigned)((kk * 2 + hi) ^ rx) << 4;
            ldsm4(af[0][0], af[0][1], af[0][2], af[0][3], sbase + arow0 + aku);
            ldsm4(af[1][0], af[1][1], af[1][2], af[1][3], sbase + arow1 + aku);
            const unsigned kadv = (unsigned)(kk * 16 * 256);
            ldsm4t(bf[0][0], bf[0][1], bf[1][0], bf[1][1], sbase + brow + bu0 + kadv);
            ldsm4t(bf[2][0], bf[2][1], bf[3][0], bf[3][1], sbase + brow + bu1 + kadv);
#pragma unroll
            for (int mt = 0; mt < 2; mt++)
#pragma unroll
                for (int nt = 0; nt < 4; nt++)
                    mma_f16(acc[mt][nt][0], acc[mt][nt][1], acc[mt][nt][2], acc[mt][nt][3],
                            af[mt][0], af[mt][1], af[mt][2], af[mt][3],
                            bf[nt][0], bf[nt][1]);
        }
        __syncthreads();
    }

    gemm_epilogue<GELU, OutT>(acc, bias, C, N, bx, by, wm, wn, lane);
}

template <bool GELU, typename OutT>
__global__ __launch_bounds__(256, 3) void gemm_s(
    const __half* __restrict__ A, const __half* __restrict__ B,
    const float* __restrict__ bias, OutT* __restrict__ C, int N, int K)
{
    gemm_body3<GELU, OutT>(A, B, bias, C, N, K, blockIdx.x, blockIdx.y);
}

template <bool GELU, typename OutT>
__global__ __launch_bounds__(256, 4) void gemm_b(
    const __half* __restrict__ A, const __half* __restrict__ B,
    const float* __restrict__ bias, OutT* __restrict__ C, int N, int K)
{
    gemm_body4<GELU, OutT>(A, B, bias, C, N, K, blockIdx.x, blockIdx.y);
}

__global__ __launch_bounds__(256, 4) void gemm_b_qkv(
    const __half* __restrict__ X,
    const __half* __restrict__ Wqh, const __half* __restrict__ Wkh, const __half* __restrict__ Wvh,
    const float* __restrict__ bq, const float* __restrict__ bk, const float* __restrict__ bv,
    __half* __restrict__ q, __half* __restrict__ k, __half* __restrict__ v)
{
    const int which = blockIdx.x / 6;
    const int bx = blockIdx.x % 6;
    const __half* B   = (which == 0) ? Wqh : (which == 1) ? Wkh : Wvh;
    const float* bias = (which == 0) ? bq  : (which == 1) ? bk  : bv;
    __half* C         = (which == 0) ? q   : (which == 1) ? k   : v;
    gemm_body4<false, __half>(X, B, bias, C, CDIM, CDIM, bx, blockIdx.y);
}

// ---------------- FP16 flash attention (static, 3-stage cp.async) -----------
__global__ __launch_bounds__(256, 2) void flash_attn_h(
    const __half* __restrict__ Q, const __half* __restrict__ K,
    const __half* __restrict__ V, __half* __restrict__ O)
{
    constexpr int SR = 72;
    constexpr unsigned TILE = 64 * SR * 2;
    constexpr unsigned STAGE = 2 * TILE;

    extern __shared__ __half smh[];
    const unsigned kvb = smem_u32(smh);

    const int h  = blockIdx.x;
    const int qb = (gridDim.y - 1) - blockIdx.y;   // heavy blocks first
    const int tid  = threadIdx.x;
    const int lane = tid & 31;
    const int w = tid >> 5;
    const int g = lane >> 2;
    const int t = lane & 3;

    const int r0 = qb * 128 + w * 16 + g;
    const int r1 = r0 + 8;

    unsigned qf[4][4];
    {
        const __half2 sc = __float2half2_rn(0.125f);
        const __half* q0p = Q + (size_t)r0 * CDIM + h * HD;
        const __half* q1p = Q + (size_t)r1 * CDIM + h * HD;
#pragma unroll
        for (int kk = 0; kk < 4; kk++) {
            __half2 x0 = __hmul2(*reinterpret_cast<const __half2*>(q0p + kk * 16 + 2 * t), sc);
            __half2 x1 = __hmul2(*reinterpret_cast<const __half2*>(q1p + kk * 16 + 2 * t), sc);
            __half2 x2 = __hmul2(*reinterpret_cast<const __half2*>(q0p + kk * 16 + 2 * t + 8), sc);
            __half2 x3 = __hmul2(*reinterpret_cast<const __half2*>(q1p + kk * 16 + 2 * t + 8), sc);
            qf[kk][0] = *reinterpret_cast<unsigned*>(&x0);
            qf[kk][1] = *reinterpret_cast<unsigned*>(&x1);
            qf[kk][2] = *reinterpret_cast<unsigned*>(&x2);
            qf[kk][3] = *reinterpret_cast<unsigned*>(&x3);
        }
    }

    const int rb = (lane & 7) | ((lane & 16) >> 1);
    const int cbh = lane & 8;
    unsigned koff[4];
#pragma unroll
    for (int j = 0; j < 4; j++)
        koff[j] = ((j * 16 + rb) * SR + cbh) * 2;
    const int vr = lane & 15;
    const int vc = (lane >> 4) << 3;
    unsigned voff[4];
#pragma unroll
    for (int j = 0; j < 4; j++)
        voff[j] = TILE + (vr * SR + j * 16 + vc) * 2;

    float o[8][4] = {};
    float m0 = -1e30f, m1 = -1e30f, l0 = 0.f, l1 = 0.f;

    const int u0 = tid * 2;
    const int ntiles = 2 * (qb + 1);

    auto prefetch = [&](int kb) {
        const unsigned dst = kvb + (unsigned)(kb % 3) * STAGE;
        const int kbase = kb * 64;
#pragma unroll
        for (int j = 0; j < 2; j++) {
            const int u = u0 + j, row = u >> 3, c = u & 7;
            const unsigned off = (unsigned)(row * SR + c * 8) * 2;
            cp16(dst + off, K + (size_t)(kbase + row) * CDIM + h * HD + c * 8);
            cp16(dst + TILE + off, V + (size_t)(kbase + row) * CDIM + h * HD + c * 8);
        }
        cp_commit();
    };

    prefetch(0);
    if (ntiles > 1) prefetch(1);

    for (int kb = 0; kb < ntiles; kb++) {
        if (kb + 1 < ntiles) cp_wait1(); else cp_wait0();
        __syncthreads();
        if (kb + 2 < ntiles) prefetch(kb + 2);

        const unsigned kbase_s = kvb + (unsigned)(kb % 3) * STAGE;

        float s[8][4] = {};
#pragma unroll
        for (int kk = 0; kk < 4; kk++) {
            const unsigned kb2 = kk * 32;
#pragma unroll
            for (int j = 0; j < 4; j++) {
                unsigned b0, b1, b2, b3;
                ldsm4(b0, b1, b2, b3, kbase_s + koff[j] + kb2);
                mma_f16(s[2 * j][0], s[2 * j][1], s[2 * j][2], s[2 * j][3],
                        qf[kk][0], qf[kk][1], qf[kk][2], qf[kk][3], b0, b1);
                mma_f16(s[2 * j + 1][0], s[2 * j + 1][1], s[2 * j + 1][2], s[2 * j + 1][3],
                        qf[kk][0], qf[kk][1], qf[kk][2], qf[kk][3], b2, b3);
            }
        }

        if (kb >= 2 * qb) {
            const int cb = kb * 64;
#pragma unroll
            for (int nt = 0; nt < 8; nt++) {
                const int c0 = cb + nt * 8 + 2 * t;
                if (c0 > r0)     s[nt][0] = -1e30f;
                if (c0 + 1 > r0) s[nt][1] = -1e30f;
                if (c0 > r1)     s[nt][2] = -1e30f;
                if (c0 + 1 > r1) s[nt][3] = -1e30f;
            }
        }

        float mx0 = -1e30f, mx1 = -1e30f;
#pragma unroll
        for (int nt = 0; nt < 8; nt++) {
            mx0 = fmaxf(mx0, fmaxf(s[nt][0], s[nt][1]));
            mx1 = fmaxf(mx1, fmaxf(s[nt][2], s[nt][3]));
        }
        mx0 = fmaxf(mx0, __shfl_xor_sync(0xffffffffu, mx0, 1));
        mx0 = fmaxf(mx0, __shfl_xor_sync(0xffffffffu, mx0, 2));
        mx1 = fmaxf(mx1, __shfl_xor_sync(0xffffffffu, mx1, 1));
        mx1 = fmaxf(mx1, __shfl_xor_sync(0xffffffffu, mx1, 2));

        const float nm0 = fmaxf(m0, mx0);
        const float nm1 = fmaxf(m1, mx1);
        const float cr0 = __expf(m0 - nm0);
        const float cr1 = __expf(m1 - nm1);
        m0 = nm0; m1 = nm1;

        float sm0 = 0.f, sm1 = 0.f;
#pragma unroll
        for (int nt = 0; nt < 8; nt++) {
            float p0 = __expf(s[nt][0] - nm0);
            float p1 = __expf(s[nt][1] - nm0);
            float p2 = __expf(s[nt][2] - nm1);
            float p3 = __expf(s[nt][3] - nm1);
            s[nt][0] = p0; s[nt][1] = p1; s[nt][2] = p2; s[nt][3] = p3;
            sm0 += p0 + p1;
            sm1 += p2 + p3;
        }
        sm0 += __shfl_xor_sync(0xffffffffu, sm0, 1);
        sm0 += __shfl_xor_sync(0xffffffffu, sm0, 2);
        sm1 += __shfl_xor_sync(0xffffffffu, sm1, 1);
        sm1 += __shfl_xor_sync(0xffffffffu, sm1, 2);
        l0 = l0 * cr0 + sm0;
        l1 = l1 * cr1 + sm1;

#pragma unroll
        for (int nt = 0; nt < 8; nt++) {
            o[nt][0] *= cr0; o[nt][1] *= cr0;
            o[nt][2] *= cr1; o[nt][3] *= cr1;
        }

#pragma unroll
        for (int kk = 0; kk < 4; kk++) {
            unsigned a0 = pack_h2(s[2 * kk][0], s[2 * kk][1]);
            unsigned a1 = pack_h2(s[2 * kk][2], s[2 * kk][3]);
            unsigned a2 = pack_h2(s[2 * kk + 1][0], s[2 * kk + 1][1]);
            unsigned a3 = pack_h2(s[2 * kk + 1][2], s[2 * kk + 1][3]);
            const unsigned kb2 = kk * 16 * SR * 2;
#pragma unroll
            for (int j = 0; j < 4; j++) {
                unsigned b0, b1, b2, b3;
                ldsm4t(b0, b1, b2, b3, kbase_s + voff[j] + kb2);
                mma_f16(o[2 * j][0], o[2 * j][1], o[2 * j][2], o[2 * j][3],
                        a0, a1, a2, a3, b0, b1);
                mma_f16(o[2 * j + 1][0], o[2 * j + 1][1], o[2 * j + 1][2], o[2 * j + 1][3],
                        a0, a1, a2, a3, b2, b3);
            }
        }
    }

    const float inv0 = 1.f / l0;
    const float inv1 = 1.f / l1;
    __half* o0p = O + (size_t)r0 * CDIM + h * HD;
    __half* o1p = O + (size_t)r1 * CDIM + h * HD;
#pragma unroll
    for (int nt = 0; nt < 8; nt++) {
        const int c = nt * 8 + 2 * t;
        *reinterpret_cast<unsigned*>(o0p + c) = pack_h2(o[nt][0] * inv0, o[nt][1] * inv0);
        *reinterpret_cast<unsigned*>(o1p + c) = pack_h2(o[nt][2] * inv1, o[nt][3] * inv1);
    }
}

// ---------------- fused residual add + LayerNorm (vectorized) ---------------
template <bool DUALOUT>
__global__ __launch_bounds__(256) void add_ln(
    const float* __restrict__ A, const float* __restrict__ Bb,
    const float* __restrict__ g, const float* __restrict__ be,
    float* __restrict__ out, __half* __restrict__ out_h)
{
    const int row = blockIdx.x;
    const int tid = threadIdx.x;
    const float* pa = A + (size_t)row * CDIM;
    const float* pb = Bb + (size_t)row * CDIM;

    float4 v = make_float4(0.f, 0.f, 0.f, 0.f);
    float s = 0.f, sq = 0.f;
    if (tid < 192) {
        float4 a = *reinterpret_cast<const float4*>(pa + tid * 4);
        float4 b = *reinterpret_cast<const float4*>(pb + tid * 4);
        v.x = a.x + b.x; v.y = a.y + b.y; v.z = a.z + b.z; v.w = a.w + b.w;
        s = v.x + v.y + v.z + v.w;
        sq = v.x * v.x + v.y * v.y + v.z * v.z + v.w * v.w;
    }
#pragma unroll
    for (int off = 16; off; off >>= 1) {
        s += __shfl_xor_sync(0xffffffffu, s, off);
        sq += __shfl_xor_sync(0xffffffffu, sq, off);
    }
    __shared__ float ss[8], ssq[8];
    int w = tid >> 5, lane = tid & 31;
    if (lane == 0) { ss[w] = s; ssq[w] = sq; }
    __syncthreads();
    if (tid < 32) {
        s = (tid < 8) ? ss[tid] : 0.f;
        sq = (tid < 8) ? ssq[tid] : 0.f;
#pragma unroll
        for (int off = 4; off; off >>= 1) {
            s += __shfl_xor_sync(0xffffffffu, s, off);
            sq += __shfl_xor_sync(0xffffffffu, sq, off);
        }
        if (tid == 0) { ss[0] = s; ssq[0] = sq; }
    }
    __syncthreads();
    const float mean = ss[0] * (1.0f / CDIM);
    const float var = ssq[0] * (1.0f / CDIM) - mean * mean;
    const float inv = rsqrtf(var + 1e-5f);
    if (tid < 192) {
        float4 gg = *reinterpret_cast<const float4*>(g + tid * 4);
        float4 bb = *reinterpret_cast<const float4*>(be + tid * 4);
        float4 r;
        r.x = (v.x - mean) * inv * gg.x + bb.x;
        r.y = (v.y - mean) * inv * gg.y + bb.y;
        r.z = (v.z - mean) * inv * gg.z + bb.z;
        r.w = (v.w - mean) * inv * gg.w + bb.w;
        *reinterpret_cast<float4*>(out + (size_t)row * CDIM + tid * 4) = r;
        if (DUALOUT) {
            uint2 u;
            u.x = pack_h2(r.x, r.y);
            u.y = pack_h2(r.z, r.w);
            *reinterpret_cast<uint2*>(out_h + (size_t)row * CDIM + tid * 4) = u;
        }
    }
}

// ---------------- launch ----------------------------------------------------
extern "C" void kernel_launch(void* const* d_in, const int* in_sizes, int n_in,
                              void* d_out, int out_size)
{
    const float* x     = (const float*)d_in[0];
    const float* Wq    = (const float*)d_in[1];
    const float* bq    = (const float*)d_in[2];
    const float* Wk    = (const float*)d_in[3];
    const float* bk    = (const float*)d_in[4];
    const float* Wv    = (const float*)d_in[5];
    const float* bv    = (const float*)d_in[6];
    const float* Wo    = (const float*)d_in[7];
    const float* bo    = (const float*)d_in[8];
    const float* ln1g  = (const float*)d_in[9];
    const float* ln1b  = (const float*)d_in[10];
    const float* W1    = (const float*)d_in[11];
    const float* b1    = (const float*)d_in[12];
    const float* W2    = (const float*)d_in[13];
    const float* b2    = (const float*)d_in[14];
    const float* ln2g  = (const float*)d_in[15];
    const float* ln2b  = (const float*)d_in[16];
    float* y = (float*)d_out;

    __half *q, *k, *v, *attn, *hh, *m1, *xh, *wq, *wk, *wv, *wo, *w1, *w2;
    float *proj, *h, *m2;
    cudaGetSymbolAddress((void**)&q,    g_q);
    cudaGetSymbolAddress((void**)&k,    g_k);
    cudaGetSymbolAddress((void**)&v,    g_v);
    cudaGetSymbolAddress((void**)&attn, g_attn);
    cudaGetSymbolAddress((void**)&proj, g_proj);
    cudaGetSymbolAddress((void**)&h,    g_h);
    cudaGetSymbolAddress((void**)&hh,   g_hh);
    cudaGetSymbolAddress((void**)&m1,   g_mlp1);
    cudaGetSymbolAddress((void**)&m2,   g_mlp2);
    cudaGetSymbolAddress((void**)&xh,   g_xh);
    cudaGetSymbolAddress((void**)&wq,   g_wq);
    cudaGetSymbolAddress((void**)&wk,   g_wk);
    cudaGetSymbolAddress((void**)&wv,   g_wv);
    cudaGetSymbolAddress((void**)&wo,   g_wo);
    cudaGetSymbolAddress((void**)&w1,   g_w1);
    cudaGetSymbolAddress((void**)&w2,   g_w2);

    const int SMEM_S  = 3 * 24576;              // 73728 (3-stage)
    const int SMEM_B  = 2 * 24576;              // 49152 (2-stage)
    const int SMEM_FA = 3 * 2 * 64 * 72 * 2;    // 55296
    cudaFuncSetAttribute(gemm_b_qkv, cudaFuncAttributeMaxDynamicSharedMemorySize, SMEM_B);
    cudaFuncSetAttribute(gemm_b<true, __half>,  cudaFuncAttributeMaxDynamicSharedMemorySize, SMEM_B);
    cudaFuncSetAttribute(gemm_s<false, float>,  cudaFuncAttributeMaxDynamicSharedMemorySize, SMEM_S);
    cudaFuncSetAttribute(flash_attn_h, cudaFuncAttributeMaxDynamicSharedMemorySize, SMEM_FA);

    // one fused convert launch: x + 6 weights -> half
    CvtArgs ca;
    ca.s[0] = { x,  xh, SEQ * CDIM };
    ca.s[1] = { Wq, wq, CDIM * CDIM };
    ca.s[2] = { Wk, wk, CDIM * CDIM };
    ca.s[3] = { Wv, wv, CDIM * CDIM };
    ca.s[4] = { Wo, wo, CDIM * CDIM };
    ca.s[5] = { W1, w1, CDIM * FDIM };
    ca.s[6] = { W2, w2, FDIM * CDIM };
    cvt_all_kernel<<<dim3(SEQ * CDIM / 4096, 7), 256>>>(ca);

    // fused QKV projection (big grid: 2-stage, 4 CTA/SM)
    gemm_b_qkv<<<dim3(18, SEQ / 64), 256, SMEM_B>>>(xh, wq, wk, wv, bq, bk, bv, q, k, v);

    // causal attention (static heavy-first)
    flash_attn_h<<<dim3(NH, SEQ / 128), 256, SMEM_FA>>>(q, k, v, attn);

    // output projection (small grid: 3-stage, 3 CTA/SM)
    gemm_s<false, float><<<dim3(CDIM / 128, SEQ / 64), 256, SMEM_S>>>(attn, wo, bo, proj, CDIM, CDIM);

    // h = LN(x + proj), plus half copy for W1
    add_ln<true><<<SEQ, 256>>>(x, proj, ln1g, ln1b, h, hh);

    // MLP1 (big grid) / MLP2 (small grid)
    gemm_b<true, __half><<<dim3(FDIM / 128, SEQ / 64), 256, SMEM_B>>>(hh, w1, b1, m1, FDIM, CDIM);
    gemm_s<false, float><<<dim3(CDIM / 128, SEQ / 64), 256, SMEM_S>>>(m1, w2, b2, m2, CDIM, FDIM);

    // y = LN(h + mlp)
    add_ln<false><<<SEQ, 256>>>(h, m2, ln2g, ln2b, y, nullptr);

    (void)in_sizes; (void)n_in; (void)out_size;
}